// round 10
// baseline (speedup 1.0000x reference)
#include <cuda_runtime.h>

// Reverse cummax along axis 1 of [B=16, H=128, W=128, C=256] fp32.
// out[b,h,w,c] = max_{h'>=h} in[b,h',w,c]
//
// FINAL (plateau-confirmed): one thread per (b, w, c4) float4 column,
// register running max, h=127..0, interleaved load/max/store with unroll 4,
// block 256 / grid 512, no cache hints. Measured best across the full
// variant matrix (R1: 80.4us kernel, DRAM 76.5%). All alternatives —
// deeper MLP (R8), phase-batched R/W bursts (R9), streaming hints (R2/R5),
// smaller blocks (R5) — were neutral or regressions. 6.0 TB/s is the
// practical mixed-R/W HBM ceiling; traffic (512MB) is provably minimal.

static constexpr int B = 16;
static constexpr int H = 128;
static constexpr int W = 128;
static constexpr int C = 256;
static constexpr int C4 = C / 4;                 // 64 float4 per (w) row
static constexpr int PLANE4 = W * C4;            // 8192 float4 per (b,h) slice
static constexpr int HSTRIDE4 = PLANE4;
static constexpr int NCOL = B * W * C4;          // 131072 columns

__global__ __launch_bounds__(256) void suffix_cummax_kernel(
    const float4* __restrict__ in, float4* __restrict__ out)
{
    int col = blockIdx.x * blockDim.x + threadIdx.x;  // grid covers exactly NCOL

    // col -> (b, w, c4): c4 fastest
    int c4 = col & (C4 - 1);
    int w  = (col >> 6) & (W - 1);       // C4 = 2^6
    int b  = col >> 13;                  // W*C4 = 2^13

    // whole tensor is 16M float4 -> int indexing is safe
    int base = b * (H * PLANE4) + w * C4 + c4;

    const float4* ip = in  + base + (H - 1) * HSTRIDE4;
    float4*       op = out + base + (H - 1) * HSTRIDE4;

    float4 run;
    run.x = -__int_as_float(0x7f800000);  // -inf
    run.y = run.x; run.z = run.x; run.w = run.x;

    #pragma unroll 4
    for (int h = H - 1; h >= 0; --h) {
        float4 v = *ip;
        run.x = fmaxf(run.x, v.x);
        run.y = fmaxf(run.y, v.y);
        run.z = fmaxf(run.z, v.z);
        run.w = fmaxf(run.w, v.w);
        *op = run;
        ip -= HSTRIDE4;
        op -= HSTRIDE4;
    }
}

extern "C" void kernel_launch(void* const* d_in, const int* in_sizes, int n_in,
                              void* d_out, int out_size)
{
    const float4* in  = (const float4*)d_in[0];
    float4*       out = (float4*)d_out;

    int threads = 256;
    int blocks  = NCOL / threads;  // 512, exact
    suffix_cummax_kernel<<<blocks, threads>>>(in, out);
}

// round 11
// speedup vs baseline: 1.0093x; 1.0093x over previous
#include <cuda_runtime.h>

// Reverse cummax along axis 1 of [B=16, H=128, W=128, C=256] fp32.
// out[b,h,w,c] = max_{h'>=h} in[b,h',w,c]
//
// FINAL (converged, 2x reproduced at 79.5/80.4us kernel, DRAM ~77%):
// one thread per (b, w, c4) float4 column, register running max, h=127..0,
// interleaved load/max/store, unroll 4, block 256 / grid 512, no cache
// hints, regs=28.
//
// Evidence of plateau: MLP depth 1..8, phase-batched 4KB R/W bursts,
// streaming cache hints, and block 128 all measured neutral-to-worse.
// 6.0-6.2 TB/s is the practical mixed read/write HBM ceiling on this part;
// DRAM traffic (512MB) is the provable minimum for this op. Compute pipes
// idle (issue ~5%). Residual wall-vs-kernel gap is harness overhead.

static constexpr int B = 16;
static constexpr int H = 128;
static constexpr int W = 128;
static constexpr int C = 256;
static constexpr int C4 = C / 4;                 // 64 float4 per (w) row
static constexpr int PLANE4 = W * C4;            // 8192 float4 per (b,h) slice
static constexpr int HSTRIDE4 = PLANE4;
static constexpr int NCOL = B * W * C4;          // 131072 columns

__global__ __launch_bounds__(256) void suffix_cummax_kernel(
    const float4* __restrict__ in, float4* __restrict__ out)
{
    int col = blockIdx.x * blockDim.x + threadIdx.x;  // grid covers exactly NCOL

    // col -> (b, w, c4): c4 fastest
    int c4 = col & (C4 - 1);
    int w  = (col >> 6) & (W - 1);       // C4 = 2^6
    int b  = col >> 13;                  // W*C4 = 2^13

    // whole tensor is 16M float4 -> int indexing is safe
    int base = b * (H * PLANE4) + w * C4 + c4;

    const float4* ip = in  + base + (H - 1) * HSTRIDE4;
    float4*       op = out + base + (H - 1) * HSTRIDE4;

    float4 run;
    run.x = -__int_as_float(0x7f800000);  // -inf
    run.y = run.x; run.z = run.x; run.w = run.x;

    #pragma unroll 4
    for (int h = H - 1; h >= 0; --h) {
        float4 v = *ip;
        run.x = fmaxf(run.x, v.x);
        run.y = fmaxf(run.y, v.y);
        run.z = fmaxf(run.z, v.z);
        run.w = fmaxf(run.w, v.w);
        *op = run;
        ip -= HSTRIDE4;
        op -= HSTRIDE4;
    }
}

extern "C" void kernel_launch(void* const* d_in, const int* in_sizes, int n_in,
                              void* d_out, int out_size)
{
    const float4* in  = (const float4*)d_in[0];
    float4*       out = (float4*)d_out;

    int threads = 256;
    int blocks  = NCOL / threads;  // 512, exact
    suffix_cummax_kernel<<<blocks, threads>>>(in, out);
}